// round 12
// baseline (speedup 1.0000x reference)
#include <cuda_runtime.h>
#include <cuda_fp16.h>
#include <cstdint>

typedef long long ll;

// ============================ helpers ============================
__device__ __forceinline__ uint32_t smem_u32(const void* p) {
    uint32_t a;
    asm("{ .reg .u64 t; cvta.to.shared.u64 t, %1; cvt.u32.u64 %0, t; }" : "=r"(a) : "l"(p));
    return a;
}
#define SWZ(o) ((o) ^ (((o) >> 3) & 0x70))

__device__ __forceinline__ void cpa16(uint32_t dst, const void* src) {
    asm volatile("cp.async.cg.shared.global [%0], [%1], 16;" :: "r"(dst), "l"(src));
}
__device__ __forceinline__ void cpa_commit() {
    asm volatile("cp.async.commit_group;");
}
template <int N>
__device__ __forceinline__ void cpa_wait() {
    asm volatile("cp.async.wait_group %0;" :: "n"(N));
}
__device__ __forceinline__ void ldmx4(uint32_t* r, uint32_t addr) {
    asm volatile("ldmatrix.sync.aligned.m8n8.x4.shared.b16 {%0,%1,%2,%3}, [%4];"
                 : "=r"(r[0]), "=r"(r[1]), "=r"(r[2]), "=r"(r[3]) : "r"(addr));
}
__device__ __forceinline__ void mma16816(float* c, const uint32_t* a, const uint32_t* b) {
    asm volatile(
        "mma.sync.aligned.m16n8k16.row.col.f32.f16.f16.f32 "
        "{%0,%1,%2,%3}, {%4,%5,%6,%7}, {%8,%9}, {%0,%1,%2,%3};"
        : "+f"(c[0]), "+f"(c[1]), "+f"(c[2]), "+f"(c[3])
        : "r"(a[0]), "r"(a[1]), "r"(a[2]), "r"(a[3]), "r"(b[0]), "r"(b[1]));
}
__device__ __forceinline__ void split2(float v, __half& h, __half& l) {
    h = __float2half_rn(v);
    l = __float2half_rn(v - __half2float(h));
}
__device__ __forceinline__ uint32_t pack_h2(__half a, __half b) {
    __half2 t = __halves2half2(a, b);
    return *(uint32_t*)&t;
}

// ============================ scratch pool ============================
static constexpr size_t NX   = (size_t)4 * 4096 * 1024;
static constexpr size_t NW   = (size_t)1024 * 1024;
static constexpr size_t NATT = (size_t)4 * 16 * 4096 * 256;

static constexpr size_t o_xh  = 0;
static constexpr size_t o_xl  = o_xh  + NX;
static constexpr size_t o_qh  = o_xl  + NX;
static constexpr size_t o_ql  = o_qh  + NX;
static constexpr size_t o_kth = o_ql  + NX;   // K transposed split (b,1024,4096)
static constexpr size_t o_ktl = o_kth + NX;
static constexpr size_t o_vth = o_ktl + NX;   // V transposed split
static constexpr size_t o_vtl = o_vth + NX;
static constexpr size_t o_ohh = o_vtl + NX;
static constexpr size_t o_ohl = o_ohh + NX;
static constexpr size_t o_wqh = o_ohl + NX;
static constexpr size_t o_wql = o_wqh + NW;
static constexpr size_t o_wkh = o_wql + NW;
static constexpr size_t o_wkl = o_wkh + NW;
static constexpr size_t o_wvh = o_wkl + NW;
static constexpr size_t o_wvl = o_wvh + NW;
static constexpr size_t o_woh = o_wvl + NW;
static constexpr size_t o_wol = o_woh + NW;
static constexpr size_t o_eh  = o_wol + NW;
static constexpr size_t o_el  = o_eh  + NW;
static constexpr size_t o_fh  = o_el  + NW;
static constexpr size_t o_fl  = o_fh  + NW;
static constexpr size_t o_kph = o_fl  + NW;
static constexpr size_t o_kpl = o_kph + NW;
static constexpr size_t o_vph = o_kpl + NW;
static constexpr size_t o_vpl = o_vph + NW;
static constexpr size_t o_ath = o_vpl + NW;
static constexpr size_t o_atl = o_ath + NATT;
static constexpr size_t POOL_ELTS = o_atl + NATT;

__device__ uint4 g_pool4[(POOL_ELTS * 2 + 15) / 16];

// ============================ convert: fp32 -> split fp16 ============================
__global__ __launch_bounds__(256) void convert_split(
    const float* __restrict__ src, __half* __restrict__ H,
    __half* __restrict__ L, int n4)
{
    int i = blockIdx.x * 256 + threadIdx.x;
    if (i >= n4) return;
    float4 v = ((const float4*)src)[i];
    __half h0, l0, h1, l1, h2, l2, h3, l3;
    split2(v.x, h0, l0); split2(v.y, h1, l1);
    split2(v.z, h2, l2); split2(v.w, h3, l3);
    ((uint2*)H)[i] = make_uint2(pack_h2(h0, h1), pack_h2(h2, h3));
    ((uint2*)L)[i] = make_uint2(pack_h2(l0, l1), pack_h2(l2, l3));
}

struct P6 { const float* s[6]; __half* h[6]; __half* l[6]; };
__global__ __launch_bounds__(256) void convert6(P6 p, int n4)
{
    const int z = blockIdx.z;
    const float* src = p.s[z];
    __half* H = p.h[z];
    __half* L = p.l[z];
    int i = blockIdx.x * 256 + threadIdx.x;
    if (i >= n4) return;
    float4 v = ((const float4*)src)[i];
    __half h0, l0, h1, l1, h2, l2, h3, l3;
    split2(v.x, h0, l0); split2(v.y, h1, l1);
    split2(v.z, h2, l2); split2(v.w, h3, l3);
    ((uint2*)H)[i] = make_uint2(pack_h2(h0, h1), pack_h2(h2, h3));
    ((uint2*)L)[i] = make_uint2(pack_h2(l0, l1), pack_h2(l2, l3));
}

// ============================ softmax(256) -> split fp16 ============================
__global__ __launch_bounds__(128) void softmax_split(
    const float* __restrict__ s, __half* __restrict__ AH, __half* __restrict__ AL)
{
    const int row = blockIdx.x * 4 + (threadIdx.x >> 5);
    const int lane = threadIdx.x & 31;
    const float* sp = s + (ll)row * 256 + lane * 8;
    float4 a = *(const float4*)sp;
    float4 b = *(const float4*)(sp + 4);
    float v[8] = {a.x, a.y, a.z, a.w, b.x, b.y, b.z, b.w};
    float mx = -3.4e38f;
#pragma unroll
    for (int i = 0; i < 8; i++) mx = fmaxf(mx, v[i]);
#pragma unroll
    for (int o = 16; o > 0; o >>= 1) mx = fmaxf(mx, __shfl_xor_sync(0xffffffffu, mx, o));
    float sum = 0.f;
#pragma unroll
    for (int i = 0; i < 8; i++) { v[i] = __expf(v[i] - mx); sum += v[i]; }
#pragma unroll
    for (int o = 16; o > 0; o >>= 1) sum += __shfl_xor_sync(0xffffffffu, sum, o);
    const float inv = 1.0f / sum;
    uint32_t hw[4], lw[4];
#pragma unroll
    for (int p = 0; p < 4; p++) {
        __half h0, l0, h1, l1;
        split2(v[2 * p] * inv, h0, l0);
        split2(v[2 * p + 1] * inv, h1, l1);
        hw[p] = pack_h2(h0, h1);
        lw[p] = pack_h2(l0, l1);
    }
    const ll o8 = (ll)row * 256 + lane * 8;
    *(uint4*)(AH + o8) = make_uint4(hw[0], hw[1], hw[2], hw[3]);
    *(uint4*)(AL + o8) = make_uint4(lw[0], lw[1], lw[2], lw[3]);
}

// ============================ old mma GEMM (validated R5 config) ============================
// Tile 128 x BN x 64; 256 thr, warp tile 32 x BN/2. Kept for small GEMMs (Kp/Vp, AV).
template <int BN, bool OUTF, bool OUTS>
__global__ __launch_bounds__(256, 1) void gemm_mma(
    const __half* __restrict__ Ah, const __half* __restrict__ Al,
    const __half* __restrict__ Bh, const __half* __restrict__ Bl,
    const float* __restrict__ bias,
    float* __restrict__ Cf, __half* __restrict__ Ch, __half* __restrict__ Cl,
    int K, int lda, int ldb, int ldc,
    ll sAo, ll sAi, ll sBo, ll sBi, ll sCo, ll sCi, int zInner, float alpha)
{
    extern __shared__ char dsm[];
    constexpr int TA = 128 * 128;
    constexpr int TBb = BN * 128;
    constexpr int STRIDE = 2 * TA + 2 * TBb;
    constexpr int WN = BN / 2;
    constexpr int WN8 = WN / 8;

    const int zo = blockIdx.z / zInner, zi = blockIdx.z - zo * zInner;
    Ah += zo * sAo + zi * sAi;  Al += zo * sAo + zi * sAi;
    Bh += zo * sBo + zi * sBi;  Bl += zo * sBo + zi * sBi;
    float* Cfz = OUTF ? (Cf + zo * sCo + zi * sCi) : nullptr;
    __half* Chz = OUTS ? (Ch + zo * sCo + zi * sCi) : nullptr;
    __half* Clz = OUTS ? (Cl + zo * sCo + zi * sCi) : nullptr;

    const int m0 = blockIdx.y * 128;
    const int n0 = blockIdx.x * BN;
    const int tid = threadIdx.x;
    const uint32_t sb = smem_u32(dsm);

    auto load_chunk = [&](int c) {
        const int buf = c & 1;
        const uint32_t bo = sb + buf * STRIDE;
        const ll kc = (ll)c * 64;
#pragma unroll
        for (int it = 0; it < 4; ++it) {
            const int u = tid + it * 256;
            const int row = u >> 3, c16 = u & 7;
            const uint32_t so = SWZ((uint32_t)(row * 128 + c16 * 16));
            const ll g = (ll)(m0 + row) * lda + kc + c16 * 8;
            cpa16(bo + so, Ah + g);
            cpa16(bo + TA + so, Al + g);
        }
#pragma unroll
        for (int it = 0; it < BN / 32; ++it) {
            const int u = tid + it * 256;
            const int row = u >> 3, c16 = u & 7;
            const uint32_t so = SWZ((uint32_t)(row * 128 + c16 * 16));
            const ll g = (ll)(n0 + row) * ldb + kc + c16 * 8;
            cpa16(bo + 2 * TA + so, Bh + g);
            cpa16(bo + 2 * TA + TBb + so, Bl + g);
        }
        cpa_commit();
    };

    const int wid = tid >> 5, lane = tid & 31;
    const int wm = wid & 3, wn = wid >> 2;
    const int m0w = wm * 32, n0w = wn * WN;
    const int lrow = lane & 15, lcol = lane >> 4;

    float acc[2][WN8][4];
#pragma unroll
    for (int i = 0; i < 2; i++)
#pragma unroll
        for (int j = 0; j < WN8; j++)
#pragma unroll
            for (int q = 0; q < 4; q++) acc[i][j][q] = 0.f;

    const int nC = K >> 6;
    load_chunk(0);

    for (int c = 0; c < nC; ++c) {
        if (c + 1 < nC) { load_chunk(c + 1); cpa_wait<1>(); }
        else           { cpa_wait<0>(); }
        __syncthreads();

        const int buf = c & 1;
        const uint32_t As_h = sb + buf * STRIDE;
        const uint32_t As_l = As_h + TA;
        const uint32_t Bs_h = As_h + 2 * TA;
        const uint32_t Bs_l = Bs_h + TBb;

#pragma unroll
        for (int k16 = 0; k16 < 4; ++k16) {
            const uint32_t kb = k16 * 32;
            uint32_t ah[2][4], al[2][4];
#pragma unroll
            for (int i = 0; i < 2; ++i) {
                const uint32_t off = SWZ((uint32_t)((m0w + i * 16 + lrow) * 128) + kb + lcol * 16);
                ldmx4(ah[i], As_h + off);
                ldmx4(al[i], As_l + off);
            }
            uint32_t bh[WN8][2], bl[WN8][2];
#pragma unroll
            for (int p = 0; p < WN8 / 2; ++p) {
                const uint32_t off = SWZ((uint32_t)((n0w + p * 16 + lrow) * 128) + kb + lcol * 16);
                uint32_t r[4];
                ldmx4(r, Bs_h + off);
                bh[2 * p][0] = r[0]; bh[2 * p][1] = r[2];
                bh[2 * p + 1][0] = r[1]; bh[2 * p + 1][1] = r[3];
                ldmx4(r, Bs_l + off);
                bl[2 * p][0] = r[0]; bl[2 * p][1] = r[2];
                bl[2 * p + 1][0] = r[1]; bl[2 * p + 1][1] = r[3];
            }
#pragma unroll
            for (int i = 0; i < 2; ++i)
#pragma unroll
                for (int j = 0; j < WN8; ++j) {
                    mma16816(acc[i][j], ah[i], bh[j]);
                    mma16816(acc[i][j], ah[i], bl[j]);
                    mma16816(acc[i][j], al[i], bh[j]);
                }
        }
        __syncthreads();
    }

    const int gID = lane >> 2;
    const int tc2 = (lane & 3) * 2;
#pragma unroll
    for (int i = 0; i < 2; ++i) {
        const int rA = m0 + m0w + i * 16 + gID;
        const int rB = rA + 8;
#pragma unroll
        for (int j = 0; j < WN8; ++j) {
            const int col = n0 + n0w + j * 8 + tc2;
            float c0 = acc[i][j][0] * alpha, c1 = acc[i][j][1] * alpha;
            float c2 = acc[i][j][2] * alpha, c3 = acc[i][j][3] * alpha;
            if (bias) {
                const float b0 = bias[col], b1 = bias[col + 1];
                c0 += b0; c1 += b1; c2 += b0; c3 += b1;
            }
            if (OUTF) {
                *(float2*)(Cfz + (ll)rA * ldc + col) = make_float2(c0, c1);
                *(float2*)(Cfz + (ll)rB * ldc + col) = make_float2(c2, c3);
            }
            if (OUTS) {
                __half h0, l0, h1, l1;
                split2(c0, h0, l0); split2(c1, h1, l1);
                *(uint32_t*)(Chz + (ll)rA * ldc + col) = pack_h2(h0, h1);
                *(uint32_t*)(Clz + (ll)rA * ldc + col) = pack_h2(l0, l1);
                split2(c2, h0, l0); split2(c3, h1, l1);
                *(uint32_t*)(Chz + (ll)rB * ldc + col) = pack_h2(h0, h1);
                *(uint32_t*)(Clz + (ll)rB * ldc + col) = pack_h2(l0, l1);
            }
        }
    }
}

// ============================ fat-tile GEMM: CTA 128x256, warp 64x64 ============================
// 8 warps = 2M x 4N. Per k16: 16 LDSM : 96 HMMA (ratio 6 vs 4 in old kernel).
// OUTT: C viewed as (16384x1024); write Ct[b,ch,tok] (per-batch 1024x4096).
template <bool OUTF, bool OUTS, bool OUTT>
__global__ __launch_bounds__(256, 1) void gemm_fat(
    const __half* __restrict__ Ah, const __half* __restrict__ Al,
    const __half* __restrict__ Bh, const __half* __restrict__ Bl,
    const float* __restrict__ bias,
    float* __restrict__ Cf, __half* __restrict__ Ch, __half* __restrict__ Cl,
    int K, int lda, int ldb, int ldc,
    ll sAo, ll sAi, ll sBo, ll sBi, ll sCo, ll sCi, int zInner, float alpha)
{
    extern __shared__ char dsm[];
    constexpr int TA = 128 * 128;          // one A split part (bytes)
    constexpr int TBb = 256 * 128;         // one B split part (bytes)
    constexpr int STRIDE = 2 * TA + 2 * TBb;  // 98304

    const int zo = blockIdx.z / zInner, zi = blockIdx.z - zo * zInner;
    Ah += zo * sAo + zi * sAi;  Al += zo * sAo + zi * sAi;
    Bh += zo * sBo + zi * sBi;  Bl += zo * sBo + zi * sBi;
    float* Cfz = OUTF ? (Cf + zo * sCo + zi * sCi) : nullptr;
    __half* Chz = (OUTS || OUTT) ? (Ch + (OUTT ? 0 : zo * sCo + zi * sCi)) : nullptr;
    __half* Clz = (OUTS || OUTT) ? (Cl + (OUTT ? 0 : zo * sCo + zi * sCi)) : nullptr;

    const int m0 = blockIdx.y * 128;
    const int n0 = blockIdx.x * 256;
    const int tid = threadIdx.x;
    const uint32_t sb = smem_u32(dsm);

    auto load_chunk = [&](int c) {
        const int buf = c & 1;
        const uint32_t bo = sb + buf * STRIDE;
        const ll kc = (ll)c * 64;
#pragma unroll
        for (int it = 0; it < 4; ++it) {           // A: 128 rows x 8 c16
            const int u = tid + it * 256;
            const int row = u >> 3, c16 = u & 7;
            const uint32_t so = SWZ((uint32_t)(row * 128 + c16 * 16));
            const ll g = (ll)(m0 + row) * lda + kc + c16 * 8;
            cpa16(bo + so, Ah + g);
            cpa16(bo + TA + so, Al + g);
        }
#pragma unroll
        for (int it = 0; it < 8; ++it) {           // B: 256 rows x 8 c16
            const int u = tid + it * 256;
            const int row = u >> 3, c16 = u & 7;
            const uint32_t so = SWZ((uint32_t)(row * 128 + c16 * 16));
            const ll g = (ll)(n0 + row) * ldb + kc + c16 * 8;
            cpa16(bo + 2 * TA + so, Bh + g);
            cpa16(bo + 2 * TA + TBb + so, Bl + g);
        }
        cpa_commit();
    };

    const int wid = tid >> 5, lane = tid & 31;
    const int wm = wid & 1, wn = wid >> 1;
    const int m0w = wm * 64, n0w = wn * 64;
    const int lrow = lane & 15, lcol = lane >> 4;

    float acc[4][8][4];
#pragma unroll
    for (int i = 0; i < 4; i++)
#pragma unroll
        for (int j = 0; j < 8; j++)
#pragma unroll
            for (int q = 0; q < 4; q++) acc[i][j][q] = 0.f;

    const int nC = K >> 6;
    load_chunk(0);

    for (int c = 0; c < nC; ++c) {
        if (c + 1 < nC) { load_chunk(c + 1); cpa_wait<1>(); }
        else           { cpa_wait<0>(); }
        __syncthreads();

        const int buf = c & 1;
        const uint32_t As_h = sb + buf * STRIDE;
        const uint32_t As_l = As_h + TA;
        const uint32_t Bs_h = As_h + 2 * TA;
        const uint32_t Bs_l = Bs_h + TBb;

#pragma unroll
        for (int k16 = 0; k16 < 4; ++k16) {
            const uint32_t kb = k16 * 32;
            uint32_t ah[4][4], al[4][4];
#pragma unroll
            for (int i = 0; i < 4; ++i) {
                const uint32_t off = SWZ((uint32_t)((m0w + i * 16 + lrow) * 128) + kb + lcol * 16);
                ldmx4(ah[i], As_h + off);
                ldmx4(al[i], As_l + off);
            }
            uint32_t bh[8][2], bl[8][2];
#pragma unroll
            for (int p = 0; p < 4; ++p) {
                const uint32_t off = SWZ((uint32_t)((n0w + p * 16 + lrow) * 128) + kb + lcol * 16);
                uint32_t r[4];
                ldmx4(r, Bs_h + off);
                bh[2 * p][0] = r[0]; bh[2 * p][1] = r[2];
                bh[2 * p + 1][0] = r[1]; bh[2 * p + 1][1] = r[3];
                ldmx4(r, Bs_l + off);
                bl[2 * p][0] = r[0]; bl[2 * p][1] = r[2];
                bl[2 * p + 1][0] = r[1]; bl[2 * p + 1][1] = r[3];
            }
#pragma unroll
            for (int i = 0; i < 4; ++i)
#pragma unroll
                for (int j = 0; j < 8; ++j) {
                    mma16816(acc[i][j], ah[i], bh[j]);
                    mma16816(acc[i][j], ah[i], bl[j]);
                    mma16816(acc[i][j], al[i], bh[j]);
                }
        }
        __syncthreads();
    }

    // ---- epilogue ----
    const int gID = lane >> 2;
    const int tc2 = (lane & 3) * 2;

    if (OUTT) {
        // stage full 128(tok) x 256(ch) tile (h and l) in smem, write transposed
        constexpr int PADC = 258;
        __half* SH = (__half*)dsm;                 // [tok 128][ch PADC]
        __half* SL = SH + 128 * PADC;
#pragma unroll
        for (int i = 0; i < 4; ++i) {
            const int r0l = m0w + i * 16 + gID;    // local token row
#pragma unroll
            for (int j = 0; j < 8; ++j) {
                const int cl = n0w + j * 8 + tc2;  // local channel col
                float c0 = acc[i][j][0] * alpha, c1 = acc[i][j][1] * alpha;
                float c2 = acc[i][j][2] * alpha, c3 = acc[i][j][3] * alpha;
                if (bias) {
                    const float b0 = bias[n0 + cl], b1 = bias[n0 + cl + 1];
                    c0 += b0; c1 += b1; c2 += b0; c3 += b1;
                }
                __half h, l;
                split2(c0, h, l); SH[r0l * PADC + cl] = h;       SL[r0l * PADC + cl] = l;
                split2(c1, h, l); SH[r0l * PADC + cl + 1] = h;   SL[r0l * PADC + cl + 1] = l;
                split2(c2, h, l); SH[(r0l + 8) * PADC + cl] = h; SL[(r0l + 8) * PADC + cl] = l;
                split2(c3, h, l); SH[(r0l + 8) * PADC + cl + 1] = h; SL[(r0l + 8) * PADC + cl + 1] = l;
            }
        }
        __syncthreads();
        const int bT = m0 >> 12;
        const int t0 = m0 & 4095;
        const int ch = tid;               // 0..255
        const ll dbase = (ll)bT * 1024 * 4096 + (ll)(n0 + ch) * 4096 + t0;
#pragma unroll
        for (int s8 = 0; s8 < 16; ++s8) {
            __half th[8], tl[8];
#pragma unroll
            for (int e = 0; e < 8; ++e) {
                const int tok = s8 * 8 + e;
                th[e] = SH[tok * PADC + ch];
                tl[e] = SL[tok * PADC + ch];
            }
            *(uint4*)(Chz + dbase + s8 * 8) = *(uint4*)th;
            *(uint4*)(Clz + dbase + s8 * 8) = *(uint4*)tl;
        }
        return;
    }

#pragma unroll
    for (int i = 0; i < 4; ++i) {
        const int rA = m0 + m0w + i * 16 + gID;
        const int rB = rA + 8;
#pragma unroll
        for (int j = 0; j < 8; ++j) {
            const int col = n0 + n0w + j * 8 + tc2;
            float c0 = acc[i][j][0] * alpha, c1 = acc[i][j][1] * alpha;
            float c2 = acc[i][j][2] * alpha, c3 = acc[i][j][3] * alpha;
            if (bias) {
                const float b0 = bias[col], b1 = bias[col + 1];
                c0 += b0; c1 += b1; c2 += b0; c3 += b1;
            }
            if (OUTF) {
                *(float2*)(Cfz + (ll)rA * ldc + col) = make_float2(c0, c1);
                *(float2*)(Cfz + (ll)rB * ldc + col) = make_float2(c2, c3);
            }
            if (OUTS) {
                __half h0, l0, h1, l1;
                split2(c0, h0, l0); split2(c1, h1, l1);
                *(uint32_t*)(Chz + (ll)rA * ldc + col) = pack_h2(h0, h1);
                *(uint32_t*)(Clz + (ll)rA * ldc + col) = pack_h2(l0, l1);
                split2(c2, h0, l0); split2(c3, h1, l1);
                *(uint32_t*)(Chz + (ll)rB * ldc + col) = pack_h2(h0, h1);
                *(uint32_t*)(Clz + (ll)rB * ldc + col) = pack_h2(l0, l1);
            }
        }
    }
}

// ============================ host launch ============================
extern "C" void kernel_launch(void* const* d_in, const int* in_sizes, int n_in,
                              void* d_out, int out_size)
{
    const float* x  = (const float*)d_in[0];
    const float* Wq = (const float*)d_in[1];
    const float* bq = (const float*)d_in[2];
    const float* Wk = (const float*)d_in[3];
    const float* bk = (const float*)d_in[4];
    const float* Wv = (const float*)d_in[5];
    const float* bv = (const float*)d_in[6];
    const float* E  = (const float*)d_in[7];
    const float* F  = (const float*)d_in[8];
    const float* Wo = (const float*)d_in[9];
    const float* bo = (const float*)d_in[10];

    float* out    = (float*)d_out;                 // (4,4096,1024)
    float* scores = out + (ll)4 * 4096 * 1024;     // (4,16,4096,256)

    __half* P;
    cudaGetSymbolAddress((void**)&P, g_pool4);
#define PP(o) (P + (o))

    auto G1  = gemm_mma<128, false, true>;    // old tile, split out (Kp/Vp)
    auto G3  = gemm_mma<64,  false, true>;    // old tile BN=64, split out (AV)
    auto F1  = gemm_fat<false, true,  false>; // fat tile, split out (Q proj)
    auto F1T = gemm_fat<false, false, true>;  // fat tile, transposed split out (K/V proj)
    auto F2  = gemm_fat<true,  false, false>; // fat tile, fp32 out (scores, out-proj)
    const int DYN128 = 2 * (2 * 128 * 128 + 2 * 128 * 128);  // 131072
    const int DYN64  = 2 * (2 * 128 * 128 + 2 * 64 * 128);   // 98304
    const int DYNF   = 2 * (2 * 128 * 128 + 2 * 256 * 128);  // 196608
    cudaFuncSetAttribute(G1,  cudaFuncAttributeMaxDynamicSharedMemorySize, DYN128);
    cudaFuncSetAttribute(G3,  cudaFuncAttributeMaxDynamicSharedMemorySize, DYN64);
    cudaFuncSetAttribute(F1,  cudaFuncAttributeMaxDynamicSharedMemorySize, DYNF);
    cudaFuncSetAttribute(F1T, cudaFuncAttributeMaxDynamicSharedMemorySize, DYNF);
    cudaFuncSetAttribute(F2,  cudaFuncAttributeMaxDynamicSharedMemorySize, DYNF);

    // 1) converts (2 launches)
    convert_split<<<(int)(NX / 4 / 256), 256>>>(x, PP(o_xh), PP(o_xl), (int)(NX / 4));
    {
        P6 p;
        p.s[0] = Wq; p.h[0] = PP(o_wqh); p.l[0] = PP(o_wql);
        p.s[1] = Wk; p.h[1] = PP(o_wkh); p.l[1] = PP(o_wkl);
        p.s[2] = Wv; p.h[2] = PP(o_wvh); p.l[2] = PP(o_wvl);
        p.s[3] = Wo; p.h[3] = PP(o_woh); p.l[3] = PP(o_wol);
        p.s[4] = E;  p.h[4] = PP(o_eh);  p.l[4] = PP(o_el);
        p.s[5] = F;  p.h[5] = PP(o_fh);  p.l[5] = PP(o_fl);
        convert6<<<dim3((int)(NW / 4 / 256), 1, 6), 256>>>(p, (int)(NW / 4));
    }

    // 2) projections (fat tile): Q normal; K,V write transposed split directly
    {
        dim3 g(4, 128, 1);
        F1<<<g, 256, DYNF>>>(PP(o_xh), PP(o_xl), PP(o_wqh), PP(o_wql), bq,
                             nullptr, PP(o_qh), PP(o_ql),
                             1024, 1024, 1024, 1024, 0, 0, 0, 0, 0, 0, 1, 1.0f);
        F1T<<<g, 256, DYNF>>>(PP(o_xh), PP(o_xl), PP(o_wkh), PP(o_wkl), bk,
                              nullptr, PP(o_kth), PP(o_ktl),
                              1024, 1024, 1024, 0, 0, 0, 0, 0, 0, 0, 1, 1.0f);
        F1T<<<g, 256, DYNF>>>(PP(o_xh), PP(o_xl), PP(o_wvh), PP(o_wvl), bv,
                              nullptr, PP(o_vth), PP(o_vtl),
                              1024, 1024, 1024, 0, 0, 0, 0, 0, 0, 0, 1, 1.0f);
    }

    // 3) Kp[b](256x1024) = E * Kt[b]^T   (old tile: better CTA count for small M)
    G1<<<dim3(8, 2, 4), 256, DYN128>>>(PP(o_eh), PP(o_el), PP(o_kth), PP(o_ktl), nullptr,
                                       nullptr, PP(o_kph), PP(o_kpl),
                                       4096, 4096, 4096, 1024,
                                       0, 0, (ll)1024 * 4096, 0, (ll)256 * 1024, 0, 1, 1.0f);
    // 4) VpT[b](1024x256) = Vt[b] * F^T
    G1<<<dim3(2, 8, 4), 256, DYN128>>>(PP(o_vth), PP(o_vtl), PP(o_fh), PP(o_fl), nullptr,
                                       nullptr, PP(o_vph), PP(o_vpl),
                                       4096, 4096, 4096, 256,
                                       (ll)1024 * 4096, 0, 0, 0, (ll)1024 * 256, 0, 1, 1.0f);

    // 5) scores[b,h](4096x256) = Q_h(4096x64) * Kp_h^T / 8  -> fp32 into d_out (fat tile)
    F2<<<dim3(1, 32, 64), 256, DYNF>>>(PP(o_qh), PP(o_ql), PP(o_kph), PP(o_kpl), nullptr,
                                       scores, nullptr, nullptr,
                                       64, 1024, 1024, 256,
                                       (ll)4096 * 1024, 64, (ll)256 * 1024, 64,
                                       (ll)16 * 4096 * 256, (ll)4096 * 256, 16, 0.125f);

    // 6) softmax -> split fp16 attn
    softmax_split<<<(4 * 16 * 4096) / 4, 128>>>(scores, PP(o_ath), PP(o_atl));

    // 7) AV: outh[b,:,h*64:](4096x64) = attn[b,h](4096x256) * VpT[b,h](64x256)^T
    G3<<<dim3(1, 32, 64), 256, DYN64>>>(PP(o_ath), PP(o_atl), PP(o_vph), PP(o_vpl), nullptr,
                                        nullptr, PP(o_ohh), PP(o_ohl),
                                        256, 256, 256, 1024,
                                        (ll)16 * 4096 * 256, (ll)4096 * 256,
                                        (ll)1024 * 256, (ll)64 * 256,
                                        (ll)4096 * 1024, 64, 16, 1.0f);

    // 8) out = outh * Wo^T + bo  (fp32 into d_out, fat tile)
    F2<<<dim3(4, 128, 1), 256, DYNF>>>(PP(o_ohh), PP(o_ohl), PP(o_woh), PP(o_wol), bo,
                                       out, nullptr, nullptr,
                                       1024, 1024, 1024, 1024,
                                       0, 0, 0, 0, 0, 0, 1, 1.0f);
#undef PP
}

// round 13
// speedup vs baseline: 1.8483x; 1.8483x over previous
#include <cuda_runtime.h>
#include <cuda_fp16.h>
#include <cstdint>

typedef long long ll;

// ============================ helpers ============================
__device__ __forceinline__ uint32_t smem_u32(const void* p) {
    uint32_t a;
    asm("{ .reg .u64 t; cvta.to.shared.u64 t, %1; cvt.u32.u64 %0, t; }" : "=r"(a) : "l"(p));
    return a;
}
#define SWZ(o) ((o) ^ (((o) >> 3) & 0x70))

__device__ __forceinline__ void cpa16(uint32_t dst, const void* src) {
    asm volatile("cp.async.cg.shared.global [%0], [%1], 16;" :: "r"(dst), "l"(src));
}
__device__ __forceinline__ void cpa_commit() {
    asm volatile("cp.async.commit_group;");
}
template <int N>
__device__ __forceinline__ void cpa_wait() {
    asm volatile("cp.async.wait_group %0;" :: "n"(N));
}
__device__ __forceinline__ void ldmx4(uint32_t* r, uint32_t addr) {
    asm volatile("ldmatrix.sync.aligned.m8n8.x4.shared.b16 {%0,%1,%2,%3}, [%4];"
                 : "=r"(r[0]), "=r"(r[1]), "=r"(r[2]), "=r"(r[3]) : "r"(addr));
}
__device__ __forceinline__ void mma16816(float* c, const uint32_t* a, const uint32_t* b) {
    asm volatile(
        "mma.sync.aligned.m16n8k16.row.col.f32.f16.f16.f32 "
        "{%0,%1,%2,%3}, {%4,%5,%6,%7}, {%8,%9}, {%0,%1,%2,%3};"
        : "+f"(c[0]), "+f"(c[1]), "+f"(c[2]), "+f"(c[3])
        : "r"(a[0]), "r"(a[1]), "r"(a[2]), "r"(a[3]), "r"(b[0]), "r"(b[1]));
}
__device__ __forceinline__ void split2(float v, __half& h, __half& l) {
    h = __float2half_rn(v);
    l = __float2half_rn(v - __half2float(h));
}
__device__ __forceinline__ uint32_t pack_h2(__half a, __half b) {
    __half2 t = __halves2half2(a, b);
    return *(uint32_t*)&t;
}

// ============================ scratch pool ============================
static constexpr size_t NX   = (size_t)4 * 4096 * 1024;
static constexpr size_t NW   = (size_t)1024 * 1024;
static constexpr size_t NATT = (size_t)4 * 16 * 4096 * 256;

static constexpr size_t o_xh  = 0;
static constexpr size_t o_xl  = o_xh  + NX;
static constexpr size_t o_qh  = o_xl  + NX;
static constexpr size_t o_ql  = o_qh  + NX;
static constexpr size_t o_kth = o_ql  + NX;   // K transposed split (b,1024,4096)
static constexpr size_t o_ktl = o_kth + NX;
static constexpr size_t o_vth = o_ktl + NX;   // V transposed split
static constexpr size_t o_vtl = o_vth + NX;
static constexpr size_t o_ohh = o_vtl + NX;
static constexpr size_t o_ohl = o_ohh + NX;
static constexpr size_t o_wqh = o_ohl + NX;
static constexpr size_t o_wql = o_wqh + NW;
static constexpr size_t o_wkh = o_wql + NW;
static constexpr size_t o_wkl = o_wkh + NW;
static constexpr size_t o_wvh = o_wkl + NW;
static constexpr size_t o_wvl = o_wvh + NW;
static constexpr size_t o_woh = o_wvl + NW;
static constexpr size_t o_wol = o_woh + NW;
static constexpr size_t o_eh  = o_wol + NW;
static constexpr size_t o_el  = o_eh  + NW;
static constexpr size_t o_fh  = o_el  + NW;
static constexpr size_t o_fl  = o_fh  + NW;
static constexpr size_t o_kph = o_fl  + NW;
static constexpr size_t o_kpl = o_kph + NW;
static constexpr size_t o_vph = o_kpl + NW;
static constexpr size_t o_vpl = o_vph + NW;
static constexpr size_t o_ath = o_vpl + NW;
static constexpr size_t o_atl = o_ath + NATT;
static constexpr size_t POOL_ELTS = o_atl + NATT;

__device__ uint4 g_pool4[(POOL_ELTS * 2 + 15) / 16];

// ============================ convert: fp32 -> split fp16 ============================
__global__ __launch_bounds__(256) void convert_split(
    const float* __restrict__ src, __half* __restrict__ H,
    __half* __restrict__ L, int n4)
{
    int i = blockIdx.x * 256 + threadIdx.x;
    if (i >= n4) return;
    float4 v = ((const float4*)src)[i];
    __half h0, l0, h1, l1, h2, l2, h3, l3;
    split2(v.x, h0, l0); split2(v.y, h1, l1);
    split2(v.z, h2, l2); split2(v.w, h3, l3);
    ((uint2*)H)[i] = make_uint2(pack_h2(h0, h1), pack_h2(h2, h3));
    ((uint2*)L)[i] = make_uint2(pack_h2(l0, l1), pack_h2(l2, l3));
}

struct P6 { const float* s[6]; __half* h[6]; __half* l[6]; };
__global__ __launch_bounds__(256) void convert6(P6 p, int n4)
{
    const int z = blockIdx.z;
    const float* src = p.s[z];
    __half* H = p.h[z];
    __half* L = p.l[z];
    int i = blockIdx.x * 256 + threadIdx.x;
    if (i >= n4) return;
    float4 v = ((const float4*)src)[i];
    __half h0, l0, h1, l1, h2, l2, h3, l3;
    split2(v.x, h0, l0); split2(v.y, h1, l1);
    split2(v.z, h2, l2); split2(v.w, h3, l3);
    ((uint2*)H)[i] = make_uint2(pack_h2(h0, h1), pack_h2(h2, h3));
    ((uint2*)L)[i] = make_uint2(pack_h2(l0, l1), pack_h2(l2, l3));
}

// ============================ softmax(256) -> split fp16 ============================
__global__ __launch_bounds__(128) void softmax_split(
    const float* __restrict__ s, __half* __restrict__ AH, __half* __restrict__ AL)
{
    const int row = blockIdx.x * 4 + (threadIdx.x >> 5);
    const int lane = threadIdx.x & 31;
    const float* sp = s + (ll)row * 256 + lane * 8;
    float4 a = *(const float4*)sp;
    float4 b = *(const float4*)(sp + 4);
    float v[8] = {a.x, a.y, a.z, a.w, b.x, b.y, b.z, b.w};
    float mx = -3.4e38f;
#pragma unroll
    for (int i = 0; i < 8; i++) mx = fmaxf(mx, v[i]);
#pragma unroll
    for (int o = 16; o > 0; o >>= 1) mx = fmaxf(mx, __shfl_xor_sync(0xffffffffu, mx, o));
    float sum = 0.f;
#pragma unroll
    for (int i = 0; i < 8; i++) { v[i] = __expf(v[i] - mx); sum += v[i]; }
#pragma unroll
    for (int o = 16; o > 0; o >>= 1) sum += __shfl_xor_sync(0xffffffffu, sum, o);
    const float inv = 1.0f / sum;
    uint32_t hw[4], lw[4];
#pragma unroll
    for (int p = 0; p < 4; p++) {
        __half h0, l0, h1, l1;
        split2(v[2 * p] * inv, h0, l0);
        split2(v[2 * p + 1] * inv, h1, l1);
        hw[p] = pack_h2(h0, h1);
        lw[p] = pack_h2(l0, l1);
    }
    const ll o8 = (ll)row * 256 + lane * 8;
    *(uint4*)(AH + o8) = make_uint4(hw[0], hw[1], hw[2], hw[3]);
    *(uint4*)(AL + o8) = make_uint4(lw[0], lw[1], lw[2], lw[3]);
}

// ============================ split-fp16 GEMM: 128 thr, tile 128x64x64, 2 CTAs/SM ============================
// C[m,n] = alpha * sum_k A[m,k]*B[n,k] (+bias[n]); A,B as hi/lo fp16 pairs (K-major).
// 4 warps (4M x 1N), warp tile 32 x 64 — same per-MAC instruction economics as the
// validated R5 kernel, but smem/CTA = 96KB -> 2 CTAs/SM for cross-CTA bubble overlap.
// OUTF: fp32 C.  OUTS: split fp16 C.  OUTT: split fp16 C transposed
//   (C viewed as (16384 x 1024) -> write Ct[b,ch,tok], b=m0/4096, per-batch 1024x4096).
template <bool OUTF, bool OUTS, bool OUTT>
__global__ __launch_bounds__(128, 2) void gemm_mma(
    const __half* __restrict__ Ah, const __half* __restrict__ Al,
    const __half* __restrict__ Bh, const __half* __restrict__ Bl,
    const float* __restrict__ bias,
    float* __restrict__ Cf, __half* __restrict__ Ch, __half* __restrict__ Cl,
    int K, int lda, int ldb, int ldc,
    ll sAo, ll sAi, ll sBo, ll sBi, ll sCo, ll sCi, int zInner, float alpha)
{
    extern __shared__ char dsm[];
    constexpr int TA = 128 * 128;   // A split part: 128 rows x 128B  (16 KB)
    constexpr int TBb = 64 * 128;   // B split part: 64 rows x 128B   (8 KB)
    constexpr int STRIDE = 2 * TA + 2 * TBb;   // 49152 per stage

    const int zo = blockIdx.z / zInner, zi = blockIdx.z - zo * zInner;
    Ah += zo * sAo + zi * sAi;  Al += zo * sAo + zi * sAi;
    Bh += zo * sBo + zi * sBi;  Bl += zo * sBo + zi * sBi;
    float* Cfz = OUTF ? (Cf + zo * sCo + zi * sCi) : nullptr;
    __half* Chz = (OUTS || OUTT) ? (Ch + (OUTT ? 0 : zo * sCo + zi * sCi)) : nullptr;
    __half* Clz = (OUTS || OUTT) ? (Cl + (OUTT ? 0 : zo * sCo + zi * sCi)) : nullptr;

    const int m0 = blockIdx.y * 128;
    const int n0 = blockIdx.x * 64;
    const int tid = threadIdx.x;
    const uint32_t sb = smem_u32(dsm);

    auto load_chunk = [&](int c) {
        const int buf = c & 1;
        const uint32_t bo = sb + buf * STRIDE;
        const ll kc = (ll)c * 64;
#pragma unroll
        for (int it = 0; it < 8; ++it) {             // A: 128 rows x 8 c16
            const int u = tid + it * 128;
            const int row = u >> 3, c16 = u & 7;
            const uint32_t so = SWZ((uint32_t)(row * 128 + c16 * 16));
            const ll g = (ll)(m0 + row) * lda + kc + c16 * 8;
            cpa16(bo + so, Ah + g);
            cpa16(bo + TA + so, Al + g);
        }
#pragma unroll
        for (int it = 0; it < 4; ++it) {             // B: 64 rows x 8 c16
            const int u = tid + it * 128;
            const int row = u >> 3, c16 = u & 7;
            const uint32_t so = SWZ((uint32_t)(row * 128 + c16 * 16));
            const ll g = (ll)(n0 + row) * ldb + kc + c16 * 8;
            cpa16(bo + 2 * TA + so, Bh + g);
            cpa16(bo + 2 * TA + TBb + so, Bl + g);
        }
        cpa_commit();
    };

    const int wid = tid >> 5, lane = tid & 31;
    const int m0w = wid * 32;                         // 4 warps in M, all share N
    const int lrow = lane & 15, lcol = lane >> 4;

    float acc[2][8][4];
#pragma unroll
    for (int i = 0; i < 2; i++)
#pragma unroll
        for (int j = 0; j < 8; j++)
#pragma unroll
            for (int q = 0; q < 4; q++) acc[i][j][q] = 0.f;

    const int nC = K >> 6;
    load_chunk(0);

    for (int c = 0; c < nC; ++c) {
        if (c + 1 < nC) { load_chunk(c + 1); cpa_wait<1>(); }
        else           { cpa_wait<0>(); }
        __syncthreads();

        const int buf = c & 1;
        const uint32_t As_h = sb + buf * STRIDE;
        const uint32_t As_l = As_h + TA;
        const uint32_t Bs_h = As_h + 2 * TA;
        const uint32_t Bs_l = Bs_h + TBb;

#pragma unroll
        for (int k16 = 0; k16 < 4; ++k16) {
            const uint32_t kb = k16 * 32;
            uint32_t ah[2][4], al[2][4];
#pragma unroll
            for (int i = 0; i < 2; ++i) {
                const uint32_t off = SWZ((uint32_t)((m0w + i * 16 + lrow) * 128) + kb + lcol * 16);
                ldmx4(ah[i], As_h + off);
                ldmx4(al[i], As_l + off);
            }
            uint32_t bh[8][2], bl[8][2];
#pragma unroll
            for (int p = 0; p < 4; ++p) {
                const uint32_t off = SWZ((uint32_t)((p * 16 + lrow) * 128) + kb + lcol * 16);
                uint32_t r[4];
                ldmx4(r, Bs_h + off);
                bh[2 * p][0] = r[0]; bh[2 * p][1] = r[2];
                bh[2 * p + 1][0] = r[1]; bh[2 * p + 1][1] = r[3];
                ldmx4(r, Bs_l + off);
                bl[2 * p][0] = r[0]; bl[2 * p][1] = r[2];
                bl[2 * p + 1][0] = r[1]; bl[2 * p + 1][1] = r[3];
            }
#pragma unroll
            for (int i = 0; i < 2; ++i)
#pragma unroll
                for (int j = 0; j < 8; ++j) {
                    mma16816(acc[i][j], ah[i], bh[j]);
                    mma16816(acc[i][j], ah[i], bl[j]);
                    mma16816(acc[i][j], al[i], bh[j]);
                }
        }
        __syncthreads();
    }

    // ---- epilogue ----
    const int gID = lane >> 2;
    const int tc2 = (lane & 3) * 2;

    if (OUTT) {
        // stage 128(tok) x 64(ch) tile (h and l) in smem, then write transposed coalesced
        constexpr int PADC = 66;
        __half* SH = (__half*)dsm;                 // [tok 128][ch PADC]
        __half* SL = SH + 128 * PADC;
#pragma unroll
        for (int i = 0; i < 2; ++i) {
            const int r0l = m0w + i * 16 + gID;    // local token row
#pragma unroll
            for (int j = 0; j < 8; ++j) {
                const int cl = j * 8 + tc2;        // local channel col
                float c0 = acc[i][j][0] * alpha, c1 = acc[i][j][1] * alpha;
                float c2 = acc[i][j][2] * alpha, c3 = acc[i][j][3] * alpha;
                if (bias) {
                    const float b0 = bias[n0 + cl], b1 = bias[n0 + cl + 1];
                    c0 += b0; c1 += b1; c2 += b0; c3 += b1;
                }
                __half h, l;
                split2(c0, h, l); SH[r0l * PADC + cl] = h;       SL[r0l * PADC + cl] = l;
                split2(c1, h, l); SH[r0l * PADC + cl + 1] = h;   SL[r0l * PADC + cl + 1] = l;
                split2(c2, h, l); SH[(r0l + 8) * PADC + cl] = h; SL[(r0l + 8) * PADC + cl] = l;
                split2(c3, h, l); SH[(r0l + 8) * PADC + cl + 1] = h; SL[(r0l + 8) * PADC + cl + 1] = l;
            }
        }
        __syncthreads();
        const int bT = m0 >> 12;
        const int t0 = m0 & 4095;
        const int ch = tid & 63;          // 0..63
        const int hf = tid >> 6;          // token half 0/1
        const ll dbase = (ll)bT * 1024 * 4096 + (ll)(n0 + ch) * 4096 + t0 + hf * 64;
#pragma unroll
        for (int s8 = 0; s8 < 8; ++s8) {
            __half th[8], tl[8];
#pragma unroll
            for (int e = 0; e < 8; ++e) {
                const int tok = hf * 64 + s8 * 8 + e;
                th[e] = SH[tok * PADC + ch];
                tl[e] = SL[tok * PADC + ch];
            }
            *(uint4*)(Chz + dbase + s8 * 8) = *(uint4*)th;
            *(uint4*)(Clz + dbase + s8 * 8) = *(uint4*)tl;
        }
        return;
    }

#pragma unroll
    for (int i = 0; i < 2; ++i) {
        const int rA = m0 + m0w + i * 16 + gID;
        const int rB = rA + 8;
#pragma unroll
        for (int j = 0; j < 8; ++j) {
            const int col = n0 + j * 8 + tc2;
            float c0 = acc[i][j][0] * alpha, c1 = acc[i][j][1] * alpha;
            float c2 = acc[i][j][2] * alpha, c3 = acc[i][j][3] * alpha;
            if (bias) {
                const float b0 = bias[col], b1 = bias[col + 1];
                c0 += b0; c1 += b1; c2 += b0; c3 += b1;
            }
            if (OUTF) {
                *(float2*)(Cfz + (ll)rA * ldc + col) = make_float2(c0, c1);
                *(float2*)(Cfz + (ll)rB * ldc + col) = make_float2(c2, c3);
            }
            if (OUTS) {
                __half h0, l0, h1, l1;
                split2(c0, h0, l0); split2(c1, h1, l1);
                *(uint32_t*)(Chz + (ll)rA * ldc + col) = pack_h2(h0, h1);
                *(uint32_t*)(Clz + (ll)rA * ldc + col) = pack_h2(l0, l1);
                split2(c2, h0, l0); split2(c3, h1, l1);
                *(uint32_t*)(Chz + (ll)rB * ldc + col) = pack_h2(h0, h1);
                *(uint32_t*)(Clz + (ll)rB * ldc + col) = pack_h2(l0, l1);
            }
        }
    }
}

// ============================ host launch ============================
extern "C" void kernel_launch(void* const* d_in, const int* in_sizes, int n_in,
                              void* d_out, int out_size)
{
    const float* x  = (const float*)d_in[0];
    const float* Wq = (const float*)d_in[1];
    const float* bq = (const float*)d_in[2];
    const float* Wk = (const float*)d_in[3];
    const float* bk = (const float*)d_in[4];
    const float* Wv = (const float*)d_in[5];
    const float* bv = (const float*)d_in[6];
    const float* E  = (const float*)d_in[7];
    const float* F  = (const float*)d_in[8];
    const float* Wo = (const float*)d_in[9];
    const float* bo = (const float*)d_in[10];

    float* out    = (float*)d_out;                 // (4,4096,1024)
    float* scores = out + (ll)4 * 4096 * 1024;     // (4,16,4096,256)

    __half* P;
    cudaGetSymbolAddress((void**)&P, g_pool4);
#define PP(o) (P + (o))

    auto G1  = gemm_mma<false, true,  false>;  // split fp16 out
    auto G1T = gemm_mma<false, false, true>;   // split fp16 out, transposed
    auto G2  = gemm_mma<true,  false, false>;  // fp32 out
    const int DYN = 2 * (2 * 128 * 128 + 2 * 64 * 128);  // 98304
    cudaFuncSetAttribute(G1,  cudaFuncAttributeMaxDynamicSharedMemorySize, DYN);
    cudaFuncSetAttribute(G1T, cudaFuncAttributeMaxDynamicSharedMemorySize, DYN);
    cudaFuncSetAttribute(G2,  cudaFuncAttributeMaxDynamicSharedMemorySize, DYN);

    // 1) converts (2 launches)
    convert_split<<<(int)(NX / 4 / 256), 256>>>(x, PP(o_xh), PP(o_xl), (int)(NX / 4));
    {
        P6 p;
        p.s[0] = Wq; p.h[0] = PP(o_wqh); p.l[0] = PP(o_wql);
        p.s[1] = Wk; p.h[1] = PP(o_wkh); p.l[1] = PP(o_wkl);
        p.s[2] = Wv; p.h[2] = PP(o_wvh); p.l[2] = PP(o_wvl);
        p.s[3] = Wo; p.h[3] = PP(o_woh); p.l[3] = PP(o_wol);
        p.s[4] = E;  p.h[4] = PP(o_eh);  p.l[4] = PP(o_el);
        p.s[5] = F;  p.h[5] = PP(o_fh);  p.l[5] = PP(o_fl);
        convert6<<<dim3((int)(NW / 4 / 256), 1, 6), 256>>>(p, (int)(NW / 4));
    }

    // 2) projections: Q normal; K,V write transposed split directly
    {
        dim3 g(16, 128, 1);
        G1<<<g, 128, DYN>>>(PP(o_xh), PP(o_xl), PP(o_wqh), PP(o_wql), bq,
                            nullptr, PP(o_qh), PP(o_ql),
                            1024, 1024, 1024, 1024, 0, 0, 0, 0, 0, 0, 1, 1.0f);
        G1T<<<g, 128, DYN>>>(PP(o_xh), PP(o_xl), PP(o_wkh), PP(o_wkl), bk,
                             nullptr, PP(o_kth), PP(o_ktl),
                             1024, 1024, 1024, 0, 0, 0, 0, 0, 0, 0, 1, 1.0f);
        G1T<<<g, 128, DYN>>>(PP(o_xh), PP(o_xl), PP(o_wvh), PP(o_wvl), bv,
                             nullptr, PP(o_vth), PP(o_vtl),
                             1024, 1024, 1024, 0, 0, 0, 0, 0, 0, 0, 1, 1.0f);
    }

    // 3) Kp[b](256x1024) = E * Kt[b]^T
    G1<<<dim3(16, 2, 4), 128, DYN>>>(PP(o_eh), PP(o_el), PP(o_kth), PP(o_ktl), nullptr,
                                     nullptr, PP(o_kph), PP(o_kpl),
                                     4096, 4096, 4096, 1024,
                                     0, 0, (ll)1024 * 4096, 0, (ll)256 * 1024, 0, 1, 1.0f);
    // 4) VpT[b](1024x256) = Vt[b] * F^T
    G1<<<dim3(4, 8, 4), 128, DYN>>>(PP(o_vth), PP(o_vtl), PP(o_fh), PP(o_fl), nullptr,
                                    nullptr, PP(o_vph), PP(o_vpl),
                                    4096, 4096, 4096, 256,
                                    (ll)1024 * 4096, 0, 0, 0, (ll)1024 * 256, 0, 1, 1.0f);

    // 5) scores[b,h](4096x256) = Q_h(4096x64) * Kp_h^T / 8  -> fp32 into d_out
    G2<<<dim3(4, 32, 64), 128, DYN>>>(PP(o_qh), PP(o_ql), PP(o_kph), PP(o_kpl), nullptr,
                                      scores, nullptr, nullptr,
                                      64, 1024, 1024, 256,
                                      (ll)4096 * 1024, 64, (ll)256 * 1024, 64,
                                      (ll)16 * 4096 * 256, (ll)4096 * 256, 16, 0.125f);

    // 6) softmax -> split fp16 attn
    softmax_split<<<(4 * 16 * 4096) / 4, 128>>>(scores, PP(o_ath), PP(o_atl));

    // 7) AV: outh[b,:,h*64:](4096x64) = attn[b,h](4096x256) * VpT[b,h](64x256)^T
    G1<<<dim3(1, 32, 64), 128, DYN>>>(PP(o_ath), PP(o_atl), PP(o_vph), PP(o_vpl), nullptr,
                                      nullptr, PP(o_ohh), PP(o_ohl),
                                      256, 256, 256, 1024,
                                      (ll)16 * 4096 * 256, (ll)4096 * 256,
                                      (ll)1024 * 256, (ll)64 * 256,
                                      (ll)4096 * 1024, 64, 16, 1.0f);

    // 8) out = outh * Wo^T + bo  (fp32 into d_out)
    G2<<<dim3(16, 128, 1), 128, DYN>>>(PP(o_ohh), PP(o_ohl), PP(o_woh), PP(o_wol), bo,
                                       out, nullptr, nullptr,
                                       1024, 1024, 1024, 1024,
                                       0, 0, 0, 0, 0, 0, 1, 1.0f);
#undef PP
}